// round 1
// baseline (speedup 1.0000x reference)
#include <cuda_runtime.h>
#include <cstdint>

// Problem constants
#define NHEAD   16
#define NGROUP  4
#define HS      64
#define SEQ     2048
#define BATCH   2
#define EDIM    1024
#define QKVN    1536      // 1024 (q) + 256 (k) + 256 (v)
#define MTOT    4096      // BATCH*SEQ
#define SM_SCALE 0.125f   // 64^-0.5

// Scratch (module-load allocated; no runtime allocation)
__device__ float g_qkv[(size_t)MTOT * QKVN];   // [b*S, 1536]: q | k | v per token
__device__ float g_attn[(size_t)MTOT * EDIM];  // attention output [b*S, E]

// ---------------- tf32 split helpers ----------------
__device__ __forceinline__ unsigned f2tf(float x) {
    unsigned r;
    asm("cvt.rna.tf32.f32 %0, %1;" : "=r"(r) : "f"(x));
    return r;
}
__device__ __forceinline__ void split_tf(float x, unsigned& hi, unsigned& lo) {
    hi = f2tf(x);
    lo = f2tf(x - __uint_as_float(hi));
}
__device__ __forceinline__ void mma8(float* c, const unsigned* a, const unsigned* b) {
    asm volatile(
        "mma.sync.aligned.m16n8k8.row.col.f32.tf32.tf32.f32 "
        "{%0,%1,%2,%3},{%4,%5,%6,%7},{%8,%9},{%0,%1,%2,%3};\n"
        : "+f"(c[0]), "+f"(c[1]), "+f"(c[2]), "+f"(c[3])
        : "r"(a[0]), "r"(a[1]), "r"(a[2]), "r"(a[3]), "r"(b[0]), "r"(b[1]));
}

// ---------------- GEMM: C[M,N] = A[M,K] @ W[N,K]^T (+bias) ----------------
// Weight rows selected from up to 3 source matrices by column boundary (QKV fusion).
#define BM 128
#define BN 64
#define BK 32
#define GPAD 36   // 32 + 4 pad: smem bank = (4*row + col) % 32 -> conflict-free frags

__global__ void __launch_bounds__(256) gemm_split_tf32(
    const float* __restrict__ A,
    const float* __restrict__ B0, const float* __restrict__ B1,
    const float* __restrict__ B2,
    int n1, int n2,
    const float* __restrict__ bias,
    float* __restrict__ C, int Kdim, int ldc)
{
    __shared__ __align__(16) float As[BM][GPAD];
    __shared__ __align__(16) float Bs[BN][GPAD];

    const int tid  = threadIdx.x;
    const int warp = tid >> 5, lane = tid & 31;
    const int bm = blockIdx.x * BM, bn = blockIdx.y * BN;
    const int wm = (warp & 3) * 32, wn = (warp >> 2) * 32;

    float acc[2][4][4];
#pragma unroll
    for (int mt = 0; mt < 2; mt++)
#pragma unroll
        for (int nt = 0; nt < 4; nt++)
#pragma unroll
            for (int r = 0; r < 4; r++) acc[mt][nt][r] = 0.f;

    const int lr  = tid >> 3;        // 0..31 row within a 32-row slab
    const int lc4 = (tid & 7) * 4;   // float4 column

    for (int kb = 0; kb < Kdim; kb += BK) {
        // Load A tile: 128x32
#pragma unroll
        for (int i = 0; i < 4; i++) {
            int row = lr + 32 * i;
            float4 v = *reinterpret_cast<const float4*>(
                A + (size_t)(bm + row) * Kdim + kb + lc4);
            *reinterpret_cast<float4*>(&As[row][lc4]) = v;
        }
        // Load B tile: 64x32 (weight rows, possibly from 3 different matrices)
#pragma unroll
        for (int i = 0; i < 2; i++) {
            int row = lr + 32 * i;
            int n = bn + row;
            const float* Wrow =
                (n < n1) ? (B0 + (size_t)n * Kdim)
                         : ((n < n2) ? (B1 + (size_t)(n - n1) * Kdim)
                                     : (B2 + (size_t)(n - n2) * Kdim));
            float4 v = *reinterpret_cast<const float4*>(Wrow + kb + lc4);
            *reinterpret_cast<float4*>(&Bs[row][lc4]) = v;
        }
        __syncthreads();

#pragma unroll
        for (int ks = 0; ks < 4; ks++) {
            const int kk = ks * 8;
            const int c0 = kk + (lane & 3);
            unsigned ahi[2][4], alo[2][4];
#pragma unroll
            for (int mt = 0; mt < 2; mt++) {
                int r0 = wm + mt * 16 + (lane >> 2);
                split_tf(As[r0][c0],       ahi[mt][0], alo[mt][0]);
                split_tf(As[r0 + 8][c0],   ahi[mt][1], alo[mt][1]);
                split_tf(As[r0][c0 + 4],   ahi[mt][2], alo[mt][2]);
                split_tf(As[r0 + 8][c0 + 4], ahi[mt][3], alo[mt][3]);
            }
#pragma unroll
            for (int nt = 0; nt < 4; nt++) {
                int n0 = wn + nt * 8 + (lane >> 2);
                unsigned bhi[2], blo[2];
                split_tf(Bs[n0][c0],     bhi[0], blo[0]);
                split_tf(Bs[n0][c0 + 4], bhi[1], blo[1]);
#pragma unroll
                for (int mt = 0; mt < 2; mt++) {
                    mma8(acc[mt][nt], ahi[mt], bhi);
                    mma8(acc[mt][nt], alo[mt], bhi);
                    mma8(acc[mt][nt], ahi[mt], blo);
                }
            }
        }
        __syncthreads();
    }

    // Epilogue
#pragma unroll
    for (int mt = 0; mt < 2; mt++) {
#pragma unroll
        for (int nt = 0; nt < 4; nt++) {
            int row = bm + wm + mt * 16 + (lane >> 2);
            int col = bn + wn + nt * 8 + 2 * (lane & 3);
            float b0 = bias ? bias[col] : 0.f;
            float b1 = bias ? bias[col + 1] : 0.f;
            float2 v0 = make_float2(acc[mt][nt][0] + b0, acc[mt][nt][1] + b1);
            float2 v1 = make_float2(acc[mt][nt][2] + b0, acc[mt][nt][3] + b1);
            *reinterpret_cast<float2*>(&C[(size_t)row * ldc + col]) = v0;
            *reinterpret_cast<float2*>(&C[(size_t)(row + 8) * ldc + col]) = v1;
        }
    }
}

// ---------------- Attention (flash-style, non-causal, no online max) ----------------
// Block = (qblock of 64 q-rows, head, batch); 4 warps, each owns 16 q-rows.
// Chunks of 32 keys. Static smem < 48KB.
#define APAD 68   // 64 + 4
#define VPAD 36   // 32 + 4

__global__ void __launch_bounds__(128) attn_kernel(
    const float* __restrict__ qkv, float* __restrict__ Obuf)
{
    __shared__ __align__(16) float Qs[64][APAD];
    __shared__ __align__(16) float Ks[32][APAD];
    __shared__ __align__(16) float Vts[64][VPAD];  // [d][key]
    __shared__ __align__(16) float Ps[64][VPAD];   // [qrow][key]

    const int tid = threadIdx.x, warp = tid >> 5, lane = tid & 31;
    const int qb = blockIdx.x, h = blockIdx.y, b = blockIdx.z;
    const int g = h >> 2;  // H/G = 4 consecutive heads per group

    const float* Qb = qkv + (size_t)b * SEQ * QKVN + h * HS;
    const float* Kb = qkv + (size_t)b * SEQ * QKVN + EDIM + g * HS;
    const float* Vb = qkv + (size_t)b * SEQ * QKVN + EDIM + NGROUP * HS + g * HS;

    // Load Q tile 64x64 once
#pragma unroll
    for (int i = 0; i < 8; i++) {
        int lin = tid + i * 128;
        int row = lin >> 4, c4 = (lin & 15) * 4;
        *reinterpret_cast<float4*>(&Qs[row][c4]) =
            *reinterpret_cast<const float4*>(Qb + (size_t)(qb * 64 + row) * QKVN + c4);
    }

    float oacc[8][4];
#pragma unroll
    for (int nt = 0; nt < 8; nt++)
#pragma unroll
        for (int r = 0; r < 4; r++) oacc[nt][r] = 0.f;
    float rs0 = 0.f, rs1 = 0.f;

    const int rA = warp * 16 + (lane >> 2);

    for (int kc = 0; kc < SEQ / 32; kc++) {
        const int k0 = kc * 32;
        // Load K chunk (32x64) and V chunk transposed (Vts[d][key])
#pragma unroll
        for (int i = 0; i < 4; i++) {
            int lin = tid + i * 128;
            int row = lin >> 4, c4 = (lin & 15) * 4;
            *reinterpret_cast<float4*>(&Ks[row][c4]) =
                *reinterpret_cast<const float4*>(Kb + (size_t)(k0 + row) * QKVN + c4);
            float4 v = *reinterpret_cast<const float4*>(
                Vb + (size_t)(k0 + row) * QKVN + c4);
            Vts[c4][row] = v.x; Vts[c4 + 1][row] = v.y;
            Vts[c4 + 2][row] = v.z; Vts[c4 + 3][row] = v.w;
        }
        __syncthreads();

        // S = Q @ K^T  (m=64 q, n=32 keys, k=64 d)
        float sacc[4][4];
#pragma unroll
        for (int nt = 0; nt < 4; nt++)
#pragma unroll
            for (int r = 0; r < 4; r++) sacc[nt][r] = 0.f;

#pragma unroll
        for (int ks = 0; ks < 8; ks++) {
            const int cc = ks * 8 + (lane & 3);
            unsigned qhi[4], qlo[4];
            split_tf(Qs[rA][cc],       qhi[0], qlo[0]);
            split_tf(Qs[rA + 8][cc],   qhi[1], qlo[1]);
            split_tf(Qs[rA][cc + 4],   qhi[2], qlo[2]);
            split_tf(Qs[rA + 8][cc + 4], qhi[3], qlo[3]);
#pragma unroll
            for (int nt = 0; nt < 4; nt++) {
                int n0 = nt * 8 + (lane >> 2);
                unsigned bhi[2], blo[2];
                split_tf(Ks[n0][cc],     bhi[0], blo[0]);
                split_tf(Ks[n0][cc + 4], bhi[1], blo[1]);
                mma8(sacc[nt], qhi, bhi);
                mma8(sacc[nt], qlo, bhi);
                mma8(sacc[nt], qhi, blo);
            }
        }

        // exp (scores are small: no max subtraction needed), rowsum, store P
#pragma unroll
        for (int nt = 0; nt < 4; nt++) {
            float p0 = __expf(sacc[nt][0] * SM_SCALE);
            float p1 = __expf(sacc[nt][1] * SM_SCALE);
            float p2 = __expf(sacc[nt][2] * SM_SCALE);
            float p3 = __expf(sacc[nt][3] * SM_SCALE);
            rs0 += p0 + p1;
            rs1 += p2 + p3;
            int col = nt * 8 + 2 * (lane & 3);
            Ps[rA][col] = p0;     Ps[rA][col + 1] = p1;
            Ps[rA + 8][col] = p2; Ps[rA + 8][col + 1] = p3;
        }
        __syncwarp();

        // O += P @ V  (m=64 q, n=64 d, k=32 keys)
#pragma unroll
        for (int ks = 0; ks < 4; ks++) {
            const int cc = ks * 8 + (lane & 3);
            unsigned phi[4], plo[4];
            split_tf(Ps[rA][cc],       phi[0], plo[0]);
            split_tf(Ps[rA + 8][cc],   phi[1], plo[1]);
            split_tf(Ps[rA][cc + 4],   phi[2], plo[2]);
            split_tf(Ps[rA + 8][cc + 4], phi[3], plo[3]);
#pragma unroll
            for (int nt = 0; nt < 8; nt++) {
                int n0 = nt * 8 + (lane >> 2);
                unsigned bhi[2], blo[2];
                split_tf(Vts[n0][cc],     bhi[0], blo[0]);
                split_tf(Vts[n0][cc + 4], bhi[1], blo[1]);
                mma8(oacc[nt], phi, bhi);
                mma8(oacc[nt], plo, bhi);
                mma8(oacc[nt], phi, blo);
            }
        }
        __syncthreads();
    }

    // Final normalize + write to g_attn laid out as [b, s, h*HS + d]
    rs0 += __shfl_xor_sync(0xffffffffu, rs0, 1);
    rs0 += __shfl_xor_sync(0xffffffffu, rs0, 2);
    rs1 += __shfl_xor_sync(0xffffffffu, rs1, 1);
    rs1 += __shfl_xor_sync(0xffffffffu, rs1, 2);
    const float inv0 = 1.f / rs0, inv1 = 1.f / rs1;

    const int row0 = qb * 64 + warp * 16 + (lane >> 2);
#pragma unroll
    for (int nt = 0; nt < 8; nt++) {
        int d = nt * 8 + 2 * (lane & 3);
        size_t o0 = ((size_t)(b * SEQ + row0)) * EDIM + h * HS + d;
        size_t o1 = ((size_t)(b * SEQ + row0 + 8)) * EDIM + h * HS + d;
        *reinterpret_cast<float2*>(&Obuf[o0]) =
            make_float2(oacc[nt][0] * inv0, oacc[nt][1] * inv0);
        *reinterpret_cast<float2*>(&Obuf[o1]) =
            make_float2(oacc[nt][2] * inv1, oacc[nt][3] * inv1);
    }
}

// ---------------- launch ----------------
extern "C" void kernel_launch(void* const* d_in, const int* in_sizes, int n_in,
                              void* d_out, int out_size)
{
    (void)in_sizes; (void)n_in; (void)out_size;
    const float* x  = (const float*)d_in[0];
    const float* Wq = (const float*)d_in[1];
    const float* Wk = (const float*)d_in[2];
    const float* Wv = (const float*)d_in[3];
    const float* Wo = (const float*)d_in[4];
    const float* bo = (const float*)d_in[5];
    float* out = (float*)d_out;

    float *qkv = nullptr, *attn = nullptr;
    cudaGetSymbolAddress((void**)&qkv, g_qkv);
    cudaGetSymbolAddress((void**)&attn, g_attn);

    // 1) fused QKV projection: [4096,1536] = x[4096,1024] @ [Wq;Wk;Wv]^T
    dim3 g1(MTOT / BM, QKVN / BN);
    gemm_split_tf32<<<g1, 256>>>(x, Wq, Wk, Wv, EDIM, EDIM + NGROUP * HS,
                                 nullptr, qkv, EDIM, QKVN);

    // 2) attention
    dim3 ga(SEQ / 64, NHEAD, BATCH);
    attn_kernel<<<ga, 128>>>(qkv, attn);

    // 3) output projection (+bias): out[4096,1024] = attn @ Wo^T + bo
    dim3 g3(MTOT / BM, EDIM / BN);
    gemm_split_tf32<<<g3, 256>>>(attn, Wo, Wo, Wo, 1 << 30, 1 << 30,
                                 bo, out, EDIM, EDIM);
}